// round 1
// baseline (speedup 1.0000x reference)
#include <cuda_runtime.h>

// out[b,j,h] = (1/N) * sum_i sum_g W[b,i,j,h,g] * x[b,i,g]
// B=16, N=32, H=64. W: 256 MiB fp32 streamed once -> pure HBM-bound.
//
// Grid: one CTA per (b,j) pair (512 CTAs). 256 threads.
// Per i, the tile W[b,i,j,:,:] is 64*64 floats = 1024 float4 = 16 KB.
// Thread t reads float4 indices {t, t+256, t+512, t+768} -> 4 partials.
// float4 index v maps to h = v>>4, g4 = v&15, so thread t owns
// h in { (t>>4) + 16k } for k=0..3, fixed g-quad g4 = t&15.
// x[b,:,:] (2048 floats = 8 KB) lives in smem; the same xv float4 feeds
// all 4 partials of a thread (g4 is fixed across k).
// Final reduce: shfl within 16-lane groups, lane (t&15)==0 writes.

#define BB 16
#define NN 32
#define HH 64

__global__ __launch_bounds__(256, 4)
void msg_nn_kernel(const float4* __restrict__ W,
                   const float4* __restrict__ X,
                   float* __restrict__ out)
{
    const int bj = blockIdx.x;      // 0..511
    const int b  = bj >> 5;         // / NN
    const int j  = bj & (NN - 1);

    __shared__ float4 xs[NN * HH / 4];   // 512 float4 = 8 KB

    const int t = threadIdx.x;      // 0..255

    // Stage x[b,:,:] into smem (512 float4, 2 per thread)
    const float4* xb = X + (size_t)b * (NN * HH / 4);
    xs[t]       = xb[t];
    xs[t + 256] = xb[t + 256];
    __syncthreads();

    const int g4 = t & 15;
    const int h0 = t >> 4;

    // Base of W[b, 0, j, 0, 0] in float4 units
    const size_t tileF4   = (size_t)HH * HH / 4;        // 1024
    const size_t iStrideF4 = (size_t)NN * tileF4;       // 32768
    const float4* Wbase = W + (size_t)b * NN * iStrideF4 + (size_t)j * tileF4;

    float acc0 = 0.f, acc1 = 0.f, acc2 = 0.f, acc3 = 0.f;

    #pragma unroll 2
    for (int i = 0; i < NN; ++i) {
        const float4* Wt = Wbase + (size_t)i * iStrideF4;
        const float4 xv = xs[i * 16 + g4];

        const float4 w0 = Wt[t];
        const float4 w1 = Wt[t + 256];
        const float4 w2 = Wt[t + 512];
        const float4 w3 = Wt[t + 768];

        acc0 += w0.x * xv.x + w0.y * xv.y + w0.z * xv.z + w0.w * xv.w;
        acc1 += w1.x * xv.x + w1.y * xv.y + w1.z * xv.z + w1.w * xv.w;
        acc2 += w2.x * xv.x + w2.y * xv.y + w2.z * xv.z + w2.w * xv.w;
        acc3 += w3.x * xv.x + w3.y * xv.y + w3.z * xv.z + w3.w * xv.w;
    }

    // Reduce the 16 g-quads per h within each contiguous 16-lane group.
    const unsigned mask = 0xFFFFFFFFu;
    #pragma unroll
    for (int off = 8; off > 0; off >>= 1) {
        acc0 += __shfl_down_sync(mask, acc0, off);
        acc1 += __shfl_down_sync(mask, acc1, off);
        acc2 += __shfl_down_sync(mask, acc2, off);
        acc3 += __shfl_down_sync(mask, acc3, off);
    }

    if (g4 == 0) {
        const float scale = 1.0f / (float)NN;
        float* o = out + (size_t)bj * HH + h0;
        o[0]  = acc0 * scale;
        o[16] = acc1 * scale;
        o[32] = acc2 * scale;
        o[48] = acc3 * scale;
    }
}

extern "C" void kernel_launch(void* const* d_in, const int* in_sizes, int n_in,
                              void* d_out, int out_size)
{
    const float4* W = (const float4*)d_in[0];   // edge_wgt [B,N,N,H,H] fp32
    const float4* X = (const float4*)d_in[1];   // node_hidden [B,N,H] fp32
    float* out = (float*)d_out;                 // [B,N,H] fp32

    dim3 grid(BB * NN);   // 512
    dim3 block(256);
    msg_nn_kernel<<<grid, block>>>(W, X, out);
}